// round 1
// baseline (speedup 1.0000x reference)
#include <cuda_runtime.h>

#define BB 2
#define NN 8192
#define MM 2048
#define KNN 32
#define C0 64
#define C1 128
#define C2 256
#define CIN 67            // 3 + C0
#define OUT_OFS (BB*MM*3) // new_xyz written first, then out

// ---------------- device scratch (no allocations allowed) ----------------
__device__ float g_xT[BB*NN*C0];   // x transposed: [b][n][c]
__device__ float g_W1t[CIN*C1];    // W1 transposed: [c][o]
__device__ float g_W2t[C1*C2];     // W2 transposed: [c][o]
__device__ int   g_idx[BB*MM*KNN]; // ball query result
__device__ float g_p[BB*MM*C2];    // pooled features pre-BN
__device__ float g_scale[C2];
__device__ float g_shift[C2];

// ---------------- prep: transposes ----------------
__global__ void prep_kernel(const float* __restrict__ x,
                            const float* __restrict__ W1,
                            const float* __restrict__ W2) {
    const int T0 = BB*C0*NN;
    const int T1 = T0 + C1*CIN;
    const int T2 = T1 + C2*C1;
    int stride = gridDim.x * blockDim.x;
    for (int e = blockIdx.x*blockDim.x + threadIdx.x; e < T2; e += stride) {
        if (e < T0) {
            int n = e % NN; int bc = e / NN; int c = bc % C0; int b = bc / C0;
            g_xT[(b*NN + n)*C0 + c] = x[e];
        } else if (e < T1) {
            int f = e - T0; int c = f % CIN; int o = f / CIN;
            g_W1t[c*C1 + o] = W1[f];
        } else {
            int f = e - T1; int c = f % C1; int o = f / C1;
            g_W2t[c*C2 + o] = W2[f];
        }
    }
}

// ---------------- FPS: one block per batch, serial over M ----------------
__global__ void __launch_bounds__(1024, 1)
fps_kernel(const float* __restrict__ xyz, float* __restrict__ out) {
    extern __shared__ float sm[];
    float* sx = sm;
    float* sy = sm + NN;
    float* sz = sm + 2*NN;
    float* rv = sm + 3*NN;            // 32 warp-partial values
    int*   ri = (int*)(rv + 32);      // 32 warp-partial indices
    int*   scur = ri + 32;

    int b = blockIdx.x;
    int tid = threadIdx.x;
    const float* base = xyz + b*NN*3;
    for (int i = tid; i < NN; i += 1024) {
        sx[i] = base[i*3 + 0];
        sy[i] = base[i*3 + 1];
        sz[i] = base[i*3 + 2];
    }
    __syncthreads();

    float px[8], py[8], pz[8], dd[8];
    int i0 = tid * 8;
    #pragma unroll
    for (int j = 0; j < 8; j++) {
        px[j] = sx[i0+j]; py[j] = sy[i0+j]; pz[j] = sz[i0+j];
        dd[j] = 1e10f;
    }

    int cur = 0;
    float* outb = out + b*MM*3;
    for (int m = 0; m < MM; m++) {
        if (tid == 0) {
            outb[m*3+0] = sx[cur];
            outb[m*3+1] = sy[cur];
            outb[m*3+2] = sz[cur];
        }
        if (m == MM-1) break;
        float lx = sx[cur], ly = sy[cur], lz = sz[cur];
        float best = -1.0f; int bi = 0;
        #pragma unroll
        for (int j = 0; j < 8; j++) {
            float dx = px[j]-lx, dy = py[j]-ly, dz = pz[j]-lz;
            // match reference order: squares then left-to-right sum, no fma
            float d2 = __fadd_rn(__fadd_rn(__fmul_rn(dx,dx), __fmul_rn(dy,dy)),
                                 __fmul_rn(dz,dz));
            float nd = fminf(dd[j], d2);
            dd[j] = nd;
            if (nd > best) { best = nd; bi = i0 + j; } // strict > keeps lowest j
        }
        #pragma unroll
        for (int off = 16; off > 0; off >>= 1) {
            float ov = __shfl_down_sync(0xffffffffu, best, off);
            int   oi = __shfl_down_sync(0xffffffffu, bi, off);
            if (ov > best || (ov == best && oi < bi)) { best = ov; bi = oi; }
        }
        if ((tid & 31) == 0) { rv[tid>>5] = best; ri[tid>>5] = bi; }
        __syncthreads();
        if (tid < 32) {
            best = rv[tid]; bi = ri[tid];
            #pragma unroll
            for (int off = 16; off > 0; off >>= 1) {
                float ov = __shfl_down_sync(0xffffffffu, best, off);
                int   oi = __shfl_down_sync(0xffffffffu, bi, off);
                if (ov > best || (ov == best && oi < bi)) { best = ov; bi = oi; }
            }
            if (tid == 0) *scur = bi;
        }
        __syncthreads();
        cur = *scur;
    }
}

// ---------------- Ball query: one warp per center, in-order first-K ----------------
__global__ void __launch_bounds__(256)
ball_kernel(const float* __restrict__ xyz, const float* __restrict__ newxyz) {
    extern __shared__ float sm[];
    float* sx = sm; float* sy = sm + NN; float* sz = sm + 2*NN;
    int blkb = blockIdx.x >> 5;   // 32 blocks per batch
    int blkc = blockIdx.x & 31;
    int tid = threadIdx.x;
    const float* base = xyz + blkb*NN*3;
    for (int i = tid; i < NN; i += 256) {
        sx[i] = base[i*3+0]; sy[i] = base[i*3+1]; sz[i] = base[i*3+2];
    }
    __syncthreads();
    int w = tid >> 5, lane = tid & 31;
    for (int s = 0; s < 8; s++) {
        int mi = blkc*64 + s*8 + w;
        int bm = blkb*MM + mi;
        float cx = newxyz[bm*3+0], cy = newxyz[bm*3+1], cz = newxyz[bm*3+2];
        int* ob = g_idx + bm*KNN;
        int cnt = 0; int first = -1;
        for (int c = 0; c < NN/32; c++) {
            int i = c*32 + lane;
            float dx = sx[i]-cx, dy = sy[i]-cy, dz = sz[i]-cz;
            float d2 = __fadd_rn(__fadd_rn(__fmul_rn(dx,dx), __fmul_rn(dy,dy)),
                                 __fmul_rn(dz,dz));
            bool in = d2 < 0.01f;   // f32(0.1*0.1 computed in python f64) == 0.01f
            unsigned msk = __ballot_sync(0xffffffffu, in);
            if (first < 0 && msk) first = c*32 + (__ffs(msk) - 1);
            if (in) {
                int slot = cnt + __popc(msk & ((1u << lane) - 1u));
                if (slot < KNN) ob[slot] = i;
            }
            cnt += __popc(msk);
            if (cnt >= KNN) break;
        }
        for (int s2 = cnt + lane; s2 < KNN; s2 += 32) ob[s2] = first;
    }
}

// ---------------- Group + 2-layer MLP + max-pool: one block per (b,m) ----------------
__global__ void __launch_bounds__(256)
group_mlp_kernel(const float* __restrict__ xyz,
                 const float* __restrict__ b1,
                 const float* __restrict__ b2,
                 const float* __restrict__ newxyz) {
    __shared__ float gT[CIN][KNN];   // [c][k]
    __shared__ float hS[C1][KNN];    // [c1][k]
    __shared__ int   sid[KNN];
    __shared__ float sctr[3];
    int bm = blockIdx.x;
    int b  = bm >> 11;               // / MM
    int t  = threadIdx.x;

    if (t < KNN) sid[t] = g_idx[bm*KNN + t];
    if (t >= 32 && t < 35) sctr[t-32] = newxyz[bm*3 + (t-32)];
    __syncthreads();

    // gather group matrix
    for (int e = t; e < CIN*KNN; e += 256) {
        int c = e >> 5, k = e & 31;
        int id = sid[k];
        float v;
        if (c < 3) v = xyz[(b*NN + id)*3 + c] - sctr[c];
        else       v = g_xT[(b*NN + id)*C0 + (c - 3)];
        gT[c][k] = v;
    }
    __syncthreads();

    // layer 1: thread = (o in [0,128), half of k)
    {
        int o = t >> 1, kh = t & 1, ko = kh * 16;
        float acc[16];
        float bb = b1[o];
        #pragma unroll
        for (int q = 0; q < 16; q++) acc[q] = bb;
        for (int c = 0; c < CIN; c++) {
            float w = g_W1t[c*C1 + o];
            const float4* gp = (const float4*)&gT[c][ko];
            #pragma unroll
            for (int q = 0; q < 4; q++) {
                float4 gv = gp[q];
                acc[q*4+0] = fmaf(w, gv.x, acc[q*4+0]);
                acc[q*4+1] = fmaf(w, gv.y, acc[q*4+1]);
                acc[q*4+2] = fmaf(w, gv.z, acc[q*4+2]);
                acc[q*4+3] = fmaf(w, gv.w, acc[q*4+3]);
            }
        }
        float4* hp = (float4*)&hS[o][ko];
        #pragma unroll
        for (int q = 0; q < 4; q++)
            hp[q] = make_float4(fmaxf(acc[q*4+0], 0.f), fmaxf(acc[q*4+1], 0.f),
                                fmaxf(acc[q*4+2], 0.f), fmaxf(acc[q*4+3], 0.f));
    }
    __syncthreads();

    // layer 2: thread = o in [0,256), 32 k-accumulators in registers
    {
        float a2[32];
        #pragma unroll
        for (int k = 0; k < 32; k++) a2[k] = 0.f;
        #pragma unroll 4
        for (int c = 0; c < C1; c++) {
            float w = g_W2t[c*C2 + t];
            const float4* hp = (const float4*)&hS[c][0];
            #pragma unroll
            for (int q = 0; q < 8; q++) {
                float4 hv = hp[q];
                a2[q*4+0] = fmaf(w, hv.x, a2[q*4+0]);
                a2[q*4+1] = fmaf(w, hv.y, a2[q*4+1]);
                a2[q*4+2] = fmaf(w, hv.z, a2[q*4+2]);
                a2[q*4+3] = fmaf(w, hv.w, a2[q*4+3]);
            }
        }
        float pm = a2[0];
        #pragma unroll
        for (int k = 1; k < 32; k++) pm = fmaxf(pm, a2[k]);
        g_p[bm*C2 + t] = pm + b2[t];   // max(h)+b2 == max(h+b2)
    }
}

// ---------------- BN stats: one block per channel ----------------
__global__ void __launch_bounds__(256)
bn_stats_kernel(const float* __restrict__ gamma, const float* __restrict__ beta) {
    int o = blockIdx.x, t = threadIdx.x;
    float s = 0.f, s2 = 0.f;
    for (int i = t; i < BB*MM; i += 256) {
        float v = g_p[i*C2 + o];
        s += v; s2 = fmaf(v, v, s2);
    }
    __shared__ float ss[32], ssq[32];
    #pragma unroll
    for (int off = 16; off > 0; off >>= 1) {
        s  += __shfl_down_sync(0xffffffffu, s, off);
        s2 += __shfl_down_sync(0xffffffffu, s2, off);
    }
    if ((t & 31) == 0) { ss[t>>5] = s; ssq[t>>5] = s2; }
    __syncthreads();
    if (t < 32) {
        float a  = (t < 8) ? ss[t]  : 0.f;
        float aq = (t < 8) ? ssq[t] : 0.f;
        #pragma unroll
        for (int off = 4; off > 0; off >>= 1) {
            a  += __shfl_down_sync(0xffffffffu, a, off);
            aq += __shfl_down_sync(0xffffffffu, aq, off);
        }
        if (t == 0) {
            const float inv_n = 1.0f / (BB*MM);
            float mean = a * inv_n;
            float var  = fmaxf(aq * inv_n - mean*mean, 0.f);
            float rstd = rsqrtf(var + 1e-5f);
            float sc = rstd * gamma[o];
            g_scale[o] = sc;
            g_shift[o] = beta[o] - mean * sc;
        }
    }
}

// ---------------- normalize + transpose to (B, C2, M) ----------------
__global__ void __launch_bounds__(256)
norm_kernel(float* __restrict__ out) {
    int b = blockIdx.x >> 8, o = blockIdx.x & 255, t = threadIdx.x;
    float sc = g_scale[o], sh = g_shift[o];
    float* ob = out + OUT_OFS + (b*C2 + o)*MM;
    const float* pb = g_p + b*MM*C2 + o;
    for (int mm = t; mm < MM; mm += 256)
        ob[mm] = fmaf(pb[mm*C2], sc, sh);
}

// ---------------- launch ----------------
extern "C" void kernel_launch(void* const* d_in, const int* in_sizes, int n_in,
                              void* d_out, int out_size) {
    const float* xyz   = (const float*)d_in[0];
    const float* x     = (const float*)d_in[1];
    const float* W1    = (const float*)d_in[2];
    const float* b1    = (const float*)d_in[3];
    const float* W2    = (const float*)d_in[4];
    const float* b2    = (const float*)d_in[5];
    const float* gamma = (const float*)d_in[6];
    const float* beta  = (const float*)d_in[7];
    float* out = (float*)d_out;

    size_t fps_smem  = (size_t)(3*NN + 32)*4 + 33*4;
    size_t ball_smem = (size_t)(3*NN)*4;
    cudaFuncSetAttribute(fps_kernel,  cudaFuncAttributeMaxDynamicSharedMemorySize, (int)fps_smem);
    cudaFuncSetAttribute(ball_kernel, cudaFuncAttributeMaxDynamicSharedMemorySize, (int)ball_smem);

    prep_kernel<<<1024, 256>>>(x, W1, W2);
    fps_kernel<<<BB, 1024, fps_smem>>>(xyz, out);
    ball_kernel<<<64, 256, ball_smem>>>(xyz, out);
    group_mlp_kernel<<<BB*MM, 256>>>(xyz, b1, b2, out);
    bn_stats_kernel<<<C2, 256>>>(gamma, beta);
    norm_kernel<<<BB*C2, 256>>>(out);
}

// round 2
// speedup vs baseline: 1.5209x; 1.5209x over previous
#include <cuda_runtime.h>

#define BB 2
#define NN 8192
#define MM 2048
#define KNN 32
#define C0 64
#define C1 128
#define C2 256
#define CIN 67            // 3 + C0
#define OUT_OFS (BB*MM*3) // new_xyz written first, then out

// ---------------- device scratch (no allocations allowed) ----------------
__device__ float g_xT[BB*NN*C0];   // x transposed: [b][n][c]
__device__ float g_W1t[CIN*C1];    // W1 transposed: [c][o]
__device__ float g_W2t[C1*C2];     // W2 transposed: [c][o]
__device__ int   g_idx[BB*MM*KNN]; // ball query result
__device__ float g_p[BB*MM*C2];    // pooled features pre-BN
__device__ float g_scale[C2];
__device__ float g_shift[C2];

// ---------------- packed f32x2 helpers (bit-exact per-lane rn) ----------------
__device__ __forceinline__ unsigned long long pk2(float lo, float hi) {
    unsigned long long r;
    asm("mov.b64 %0, {%1, %2};" : "=l"(r) : "f"(lo), "f"(hi));
    return r;
}
__device__ __forceinline__ void upk2(unsigned long long v, float& lo, float& hi) {
    asm("mov.b64 {%0, %1}, %2;" : "=f"(lo), "=f"(hi) : "l"(v));
}
__device__ __forceinline__ unsigned long long addx2(unsigned long long a, unsigned long long b) {
    unsigned long long r;
    asm("add.rn.f32x2 %0, %1, %2;" : "=l"(r) : "l"(a), "l"(b));
    return r;
}
__device__ __forceinline__ unsigned long long mulx2(unsigned long long a, unsigned long long b) {
    unsigned long long r;
    asm("mul.rn.f32x2 %0, %1, %2;" : "=l"(r) : "l"(a), "l"(b));
    return r;
}

// ---------------- prep: transposes ----------------
__global__ void prep_kernel(const float* __restrict__ x,
                            const float* __restrict__ W1,
                            const float* __restrict__ W2) {
    const int T0 = BB*C0*NN;
    const int T1 = T0 + C1*CIN;
    const int T2 = T1 + C2*C1;
    int stride = gridDim.x * blockDim.x;
    for (int e = blockIdx.x*blockDim.x + threadIdx.x; e < T2; e += stride) {
        if (e < T0) {
            int n = e % NN; int bc = e / NN; int c = bc % C0; int b = bc / C0;
            g_xT[(b*NN + n)*C0 + c] = x[e];
        } else if (e < T1) {
            int f = e - T0; int c = f % CIN; int o = f / CIN;
            g_W1t[c*C1 + o] = W1[f];
        } else {
            int f = e - T1; int c = f % C1; int o = f / C1;
            g_W2t[c*C2 + o] = W2[f];
        }
    }
}

// ---------------- FPS: one block per batch, serial over M ----------------
// Per-thread 8 points packed as 4x f32x2 per coordinate. Distances computed
// with packed rn ops (bit-exact to reference order). Argmax via
// redux.sync.max.u32 on float bits (nonneg -> order-preserving), tie-break
// lowest index via lowest lane / lowest warp (index-ascending layout).
// Single barrier per iteration with double-buffered warp partials.
__global__ void __launch_bounds__(1024, 1)
fps_kernel(const float* __restrict__ xyz, float* __restrict__ out) {
    extern __shared__ float sm[];
    float* sx = sm;
    float* sy = sm + NN;
    float* sz = sm + 2*NN;
    unsigned* rv = (unsigned*)(sm + 3*NN);  // [2][32] value bits
    int*      ri = (int*)(rv + 64);         // [2][32] indices

    int b = blockIdx.x;
    int tid = threadIdx.x;
    int lane = tid & 31, wid = tid >> 5;
    const float* base = xyz + b*NN*3;
    for (int i = tid; i < NN; i += 1024) {
        sx[i] = base[i*3 + 0];
        sy[i] = base[i*3 + 1];
        sz[i] = base[i*3 + 2];
    }
    __syncthreads();

    int i0 = tid * 8;
    unsigned long long pxp[4], pyp[4], pzp[4];
    float dd[8];
    #pragma unroll
    for (int q = 0; q < 4; q++) {
        pxp[q] = pk2(sx[i0+2*q], sx[i0+2*q+1]);
        pyp[q] = pk2(sy[i0+2*q], sy[i0+2*q+1]);
        pzp[q] = pk2(sz[i0+2*q], sz[i0+2*q+1]);
    }
    #pragma unroll
    for (int j = 0; j < 8; j++) dd[j] = 1e10f;

    int cur = 0;
    float* outb = out + b*MM*3;
    for (int m = 0; m < MM; m++) {
        if (tid == 0) {
            outb[m*3+0] = sx[cur];
            outb[m*3+1] = sy[cur];
            outb[m*3+2] = sz[cur];
        }
        if (m == MM-1) break;
        float lx = sx[cur], ly = sy[cur], lz = sz[cur];
        unsigned long long cX = pk2(-lx, -lx);
        unsigned long long cY = pk2(-ly, -ly);
        unsigned long long cZ = pk2(-lz, -lz);

        // update: dd[j] = min(dd[j], ((dx*dx + dy*dy) + dz*dz))  (exact ref order)
        #pragma unroll
        for (int q = 0; q < 4; q++) {
            unsigned long long dx = addx2(pxp[q], cX);
            unsigned long long dy = addx2(pyp[q], cY);
            unsigned long long dz = addx2(pzp[q], cZ);
            unsigned long long xx = mulx2(dx, dx);
            unsigned long long yy = mulx2(dy, dy);
            unsigned long long zz = mulx2(dz, dz);
            unsigned long long d2 = addx2(addx2(xx, yy), zz);
            float a, c;
            upk2(d2, a, c);
            dd[2*q]   = fminf(dd[2*q],   a);
            dd[2*q+1] = fminf(dd[2*q+1], c);
        }

        // stage 1: per-thread tree max, warp redux, leader publishes
        float m01 = fmaxf(dd[0], dd[1]);
        float m23 = fmaxf(dd[2], dd[3]);
        float m45 = fmaxf(dd[4], dd[5]);
        float m67 = fmaxf(dd[6], dd[7]);
        float mx  = fmaxf(fmaxf(m01, m23), fmaxf(m45, m67));
        unsigned v = __float_as_uint(mx);
        unsigned g = __reduce_max_sync(0xffffffffu, v);
        unsigned bal = __ballot_sync(0xffffffffu, v == g);
        int buf = m & 1;
        if (lane == __ffs(bal) - 1) {
            int jj = 0;
            #pragma unroll
            for (int j = 7; j >= 0; --j)
                if (__float_as_uint(dd[j]) == g) jj = j;  // lowest matching j
            rv[buf*32 + wid] = g;
            ri[buf*32 + wid] = i0 + jj;
        }
        __syncthreads();

        // stage 2: every warp redundantly reduces the 32 warp partials
        unsigned pv = rv[buf*32 + lane];
        int      pi = ri[buf*32 + lane];
        unsigned gg = __reduce_max_sync(0xffffffffu, pv);
        unsigned b2 = __ballot_sync(0xffffffffu, pv == gg);
        cur = __shfl_sync(0xffffffffu, pi, __ffs(b2) - 1);
    }
}

// ---------------- Ball query: one warp per center, in-order first-K ----------------
__global__ void __launch_bounds__(256)
ball_kernel(const float* __restrict__ xyz, const float* __restrict__ newxyz) {
    extern __shared__ float sm[];
    float* sx = sm; float* sy = sm + NN; float* sz = sm + 2*NN;
    int blkb = blockIdx.x >> 5;   // 32 blocks per batch
    int blkc = blockIdx.x & 31;
    int tid = threadIdx.x;
    const float* base = xyz + blkb*NN*3;
    for (int i = tid; i < NN; i += 256) {
        sx[i] = base[i*3+0]; sy[i] = base[i*3+1]; sz[i] = base[i*3+2];
    }
    __syncthreads();
    int w = tid >> 5, lane = tid & 31;
    for (int s = 0; s < 8; s++) {
        int mi = blkc*64 + s*8 + w;
        int bm = blkb*MM + mi;
        float cx = newxyz[bm*3+0], cy = newxyz[bm*3+1], cz = newxyz[bm*3+2];
        int* ob = g_idx + bm*KNN;
        int cnt = 0; int first = -1;
        for (int c = 0; c < NN/32; c++) {
            int i = c*32 + lane;
            float dx = sx[i]-cx, dy = sy[i]-cy, dz = sz[i]-cz;
            float d2 = __fadd_rn(__fadd_rn(__fmul_rn(dx,dx), __fmul_rn(dy,dy)),
                                 __fmul_rn(dz,dz));
            bool in = d2 < 0.01f;
            unsigned msk = __ballot_sync(0xffffffffu, in);
            if (first < 0 && msk) first = c*32 + (__ffs(msk) - 1);
            if (in) {
                int slot = cnt + __popc(msk & ((1u << lane) - 1u));
                if (slot < KNN) ob[slot] = i;
            }
            cnt += __popc(msk);
            if (cnt >= KNN) break;
        }
        for (int s2 = cnt + lane; s2 < KNN; s2 += 32) ob[s2] = first;
    }
}

// ---------------- Group + 2-layer MLP + max-pool: one block per (b,m) ----------------
__global__ void __launch_bounds__(256)
group_mlp_kernel(const float* __restrict__ xyz,
                 const float* __restrict__ b1,
                 const float* __restrict__ b2,
                 const float* __restrict__ newxyz) {
    __shared__ float gT[CIN][KNN];   // [c][k]
    __shared__ float hS[C1][KNN];    // [c1][k]
    __shared__ int   sid[KNN];
    __shared__ float sctr[3];
    int bm = blockIdx.x;
    int b  = bm >> 11;               // / MM
    int t  = threadIdx.x;

    if (t < KNN) sid[t] = g_idx[bm*KNN + t];
    if (t >= 32 && t < 35) sctr[t-32] = newxyz[bm*3 + (t-32)];
    __syncthreads();

    for (int e = t; e < CIN*KNN; e += 256) {
        int c = e >> 5, k = e & 31;
        int id = sid[k];
        float v;
        if (c < 3) v = xyz[(b*NN + id)*3 + c] - sctr[c];
        else       v = g_xT[(b*NN + id)*C0 + (c - 3)];
        gT[c][k] = v;
    }
    __syncthreads();

    // layer 1: thread = (o in [0,128), half of k)
    {
        int o = t >> 1, kh = t & 1, ko = kh * 16;
        float acc[16];
        float bb = b1[o];
        #pragma unroll
        for (int q = 0; q < 16; q++) acc[q] = bb;
        for (int c = 0; c < CIN; c++) {
            float w = g_W1t[c*C1 + o];
            const float4* gp = (const float4*)&gT[c][ko];
            #pragma unroll
            for (int q = 0; q < 4; q++) {
                float4 gv = gp[q];
                acc[q*4+0] = fmaf(w, gv.x, acc[q*4+0]);
                acc[q*4+1] = fmaf(w, gv.y, acc[q*4+1]);
                acc[q*4+2] = fmaf(w, gv.z, acc[q*4+2]);
                acc[q*4+3] = fmaf(w, gv.w, acc[q*4+3]);
            }
        }
        float4* hp = (float4*)&hS[o][ko];
        #pragma unroll
        for (int q = 0; q < 4; q++)
            hp[q] = make_float4(fmaxf(acc[q*4+0], 0.f), fmaxf(acc[q*4+1], 0.f),
                                fmaxf(acc[q*4+2], 0.f), fmaxf(acc[q*4+3], 0.f));
    }
    __syncthreads();

    // layer 2: thread = o in [0,256), 32 k-accumulators in registers
    {
        float a2[32];
        #pragma unroll
        for (int k = 0; k < 32; k++) a2[k] = 0.f;
        #pragma unroll 4
        for (int c = 0; c < C1; c++) {
            float w = g_W2t[c*C2 + t];
            const float4* hp = (const float4*)&hS[c][0];
            #pragma unroll
            for (int q = 0; q < 8; q++) {
                float4 hv = hp[q];
                a2[q*4+0] = fmaf(w, hv.x, a2[q*4+0]);
                a2[q*4+1] = fmaf(w, hv.y, a2[q*4+1]);
                a2[q*4+2] = fmaf(w, hv.z, a2[q*4+2]);
                a2[q*4+3] = fmaf(w, hv.w, a2[q*4+3]);
            }
        }
        float pm = a2[0];
        #pragma unroll
        for (int k = 1; k < 32; k++) pm = fmaxf(pm, a2[k]);
        g_p[bm*C2 + t] = pm + b2[t];   // max(h)+b2 == max(h+b2)
    }
}

// ---------------- BN stats: one block per channel ----------------
__global__ void __launch_bounds__(256)
bn_stats_kernel(const float* __restrict__ gamma, const float* __restrict__ beta) {
    int o = blockIdx.x, t = threadIdx.x;
    float s = 0.f, s2 = 0.f;
    for (int i = t; i < BB*MM; i += 256) {
        float v = g_p[i*C2 + o];
        s += v; s2 = fmaf(v, v, s2);
    }
    __shared__ float ss[32], ssq[32];
    #pragma unroll
    for (int off = 16; off > 0; off >>= 1) {
        s  += __shfl_down_sync(0xffffffffu, s, off);
        s2 += __shfl_down_sync(0xffffffffu, s2, off);
    }
    if ((t & 31) == 0) { ss[t>>5] = s; ssq[t>>5] = s2; }
    __syncthreads();
    if (t < 32) {
        float a  = (t < 8) ? ss[t]  : 0.f;
        float aq = (t < 8) ? ssq[t] : 0.f;
        #pragma unroll
        for (int off = 4; off > 0; off >>= 1) {
            a  += __shfl_down_sync(0xffffffffu, a, off);
            aq += __shfl_down_sync(0xffffffffu, aq, off);
        }
        if (t == 0) {
            const float inv_n = 1.0f / (BB*MM);
            float mean = a * inv_n;
            float var  = fmaxf(aq * inv_n - mean*mean, 0.f);
            float rstd = rsqrtf(var + 1e-5f);
            float sc = rstd * gamma[o];
            g_scale[o] = sc;
            g_shift[o] = beta[o] - mean * sc;
        }
    }
}

// ---------------- normalize + transpose to (B, C2, M) ----------------
__global__ void __launch_bounds__(256)
norm_kernel(float* __restrict__ out) {
    int b = blockIdx.x >> 8, o = blockIdx.x & 255, t = threadIdx.x;
    float sc = g_scale[o], sh = g_shift[o];
    float* ob = out + OUT_OFS + (b*C2 + o)*MM;
    const float* pb = g_p + b*MM*C2 + o;
    for (int mm = t; mm < MM; mm += 256)
        ob[mm] = fmaf(pb[mm*C2], sc, sh);
}

// ---------------- launch ----------------
extern "C" void kernel_launch(void* const* d_in, const int* in_sizes, int n_in,
                              void* d_out, int out_size) {
    const float* xyz   = (const float*)d_in[0];
    const float* x     = (const float*)d_in[1];
    const float* W1    = (const float*)d_in[2];
    const float* b1    = (const float*)d_in[3];
    const float* W2    = (const float*)d_in[4];
    const float* b2    = (const float*)d_in[5];
    const float* gamma = (const float*)d_in[6];
    const float* beta  = (const float*)d_in[7];
    float* out = (float*)d_out;

    size_t fps_smem  = (size_t)(3*NN)*4 + 64*4 + 64*4;
    size_t ball_smem = (size_t)(3*NN)*4;
    cudaFuncSetAttribute(fps_kernel,  cudaFuncAttributeMaxDynamicSharedMemorySize, (int)fps_smem);
    cudaFuncSetAttribute(ball_kernel, cudaFuncAttributeMaxDynamicSharedMemorySize, (int)ball_smem);

    prep_kernel<<<1024, 256>>>(x, W1, W2);
    fps_kernel<<<BB, 1024, fps_smem>>>(xyz, out);
    ball_kernel<<<64, 256, ball_smem>>>(xyz, out);
    group_mlp_kernel<<<BB*MM, 256>>>(xyz, b1, b2, out);
    bn_stats_kernel<<<C2, 256>>>(gamma, beta);
    norm_kernel<<<BB*C2, 256>>>(out);
}